// round 14
// baseline (speedup 1.0000x reference)
#include <cuda_runtime.h>
#include <cstdint>

// D3PM q_sample — bit-exact vs JAX threefry, partitionable mode:
//   split:  key_i = (o0, o1) of threefry2x32((0,42), (0, i))     [foldlike]
//   bits32: bits[i] = o0 ^ o1 of threefry2x32(key, (0, flat_idx)),
//           flat_idx row-major over (B, L, N).
//
// Output (float32): [0,R) noised_structure, [R,2R) noised_sequence, [2R,2R+B) t.
//
// Pruning theorem (exact): argmax of gumbel+logits is ALWAYS x0 or MASK, so 2
// RNG draws per element suffice. Ties -> lower class index.
//
// R13 lesson: instruction count (5 logf/elem) is the binding limit, not
// occupancy. This round: MARGIN-GUARDED MONOTONE COMPARE.
//   reference: vx = -logf(w1)+la  vs  vm = -logf(w2)+lm,  w = -logf(f)
//   real-arithmetic equivalent:  w2 <> w1 * exp(lm-la),
//   and exp(lm-la) = (1-a+eps)/(a+eps) up to ~5e-7 relative.
//   All fp32 rounding moves the boundary by <= ~1e-5 relative, so with
//   C = (1-a+eps)/(a+eps):
//     w2 > w1*C*(1+1e-4)  -> reference surely picked x0
//     w2 < w1*C*(1-1e-4)  -> surely MASK
//     else (P ~ 3e-5)     -> exact fallback (2 extra logf, bit-identical
//                            compare + first-max tie-break)
//   Fast path: 2 logf + 1 fmul per element; la/lm/exp eliminated.

#define TINYF  1.17549435e-38f
#define EPSF   1e-10f
#define MARGIN 1e-4f

__host__ __device__ __forceinline__ unsigned rotl32(unsigned x, int r) {
#ifdef __CUDA_ARCH__
    return __funnelshift_l(x, x, r);
#else
    return (x << r) | (x >> (32 - r));
#endif
}

// Standard threefry2x32, 20 rounds (matches jax/_src/prng.py lowering).
__host__ __device__ __forceinline__ void threefry2x32(
    unsigned k0, unsigned k1, unsigned m0, unsigned m1,
    unsigned& o0, unsigned& o1)
{
    const unsigned ks2 = 0x1BD11BDAu ^ k0 ^ k1;
    unsigned x0 = m0 + k0;
    unsigned x1 = m1 + k1;
#define TF_R(r) { x0 += x1; x1 = rotl32(x1, (r)) ^ x0; }
    TF_R(13) TF_R(15) TF_R(26) TF_R(6)
    x0 += k1;  x1 += ks2 + 1u;
    TF_R(17) TF_R(29) TF_R(16) TF_R(24)
    x0 += ks2; x1 += k0 + 2u;
    TF_R(13) TF_R(15) TF_R(26) TF_R(6)
    x0 += k0;  x1 += k1 + 3u;
    TF_R(17) TF_R(29) TF_R(16) TF_R(24)
    x0 += k1;  x1 += ks2 + 4u;
    TF_R(13) TF_R(15) TF_R(26) TF_R(6)
    x0 += ks2; x1 += k0 + 5u;
#undef TF_R
    o0 = x0; o1 = x1;
}

__device__ __forceinline__ unsigned jax_bits32(unsigned ka, unsigned kb, unsigned i) {
    unsigned o0, o1;
    threefry2x32(ka, kb, 0u, i, o0, o1);
    return o0 ^ o1;
}

// Inner gumbel stage, bit-identical to the reference's -logf(f):
//   u = bitcast((bits>>9)|0x3f800000)-1; f = max(tiny, u+tiny)  [(1-tiny)->1.0f]
__device__ __forceinline__ float w_from_bits(unsigned bits) {
    float u = __uint_as_float(0x3f800000u | (bits >> 9)) - 1.0f;
    float f = fmaxf(TINYF, u + TINYF);
    return -logf(f);          // w > 0 always (f < 1)
}

// One element. C = (1-a+eps)/(a+eps); a needed only for the rare fallback.
__device__ __forceinline__ float sample_one(
    int r, int x0, float C, float a,
    unsigned ka, unsigned kb, int N, int MASK)
{
    if (x0 == MASK) return (float)x0;   // combined channel always wins
    unsigned base = (unsigned)r * (unsigned)N;
    unsigned b1 = jax_bits32(ka, kb, base + (unsigned)x0);
    unsigned b2 = jax_bits32(ka, kb, base + (unsigned)MASK);
    float w1 = w_from_bits(b1);
    float w2 = w_from_bits(b2);

    float thr = w1 * C;
    if (w2 > thr * (1.0f + MARGIN)) return (float)x0;    // vx > vm surely
    if (w2 < thr * (1.0f - MARGIN)) return (float)MASK;  // vm > vx surely

    // exact fallback (rare): replicate the reference computation bit-for-bit
    float la = logf(a + EPSF);
    float lm = logf((1.0f - a) + EPSF);
    float vx = -logf(w1) + la;
    float vm = -logf(w2) + lm;
    if (vx > vm) return (float)x0;
    if (vm > vx) return (float)MASK;
    return (float)((x0 < MASK) ? x0 : MASK);   // argmax first-max tie-break
}

__global__ __launch_bounds__(256)
void d3pm_kernel(const int* __restrict__ pA, const int* __restrict__ pB,
                 const int* __restrict__ t, const float* __restrict__ alpha,
                 float* __restrict__ out,
                 unsigned ksa, unsigned ksb,
                 unsigned kqa, unsigned kqb,
                 int rows, int Bv, int shift, int L, int fast)
{
    // per-warp swap detect (no block sync): which big array is structure?
    // (sequence values always <= 32; structure exceeds 32 w.p. 1-8e-20)
    int lane = threadIdx.x & 31;
    int v = (lane < 16) ? pA[lane] : pB[lane - 16];
    unsigned big = __ballot_sync(0xffffffffu, v > 32);
    const bool swap = ((big & 0xFFFFu) == 0u);
    const int* structure = swap ? pB : pA;
    const int* sequence  = swap ? pA : pB;

    const int total = 2 * rows + Bv;
    const int gt    = blockIdx.x * blockDim.x + threadIdx.x;

    if (fast) {
        // 2 elements per thread; groups 2-aligned, never straddle segments
        // (rows % 2 == 0) nor batch boundaries (L % 2 == 0, r0 even).
        int j = gt * 2;
        if (j >= total) return;

        if (j < 2 * rows) {
            const bool isS = (j < rows);
            const int  r0  = isS ? j : j - rows;
            const int  N    = isS ? 516 : 33;
            const int  MASK = isS ? 3   : 32;
            const unsigned ka = isS ? ksa : kqa;
            const unsigned kb = isS ? ksb : kqb;
            const int* src = isS ? structure : sequence;

            // one batch for the pair: one t/alpha load + one fast division
            int   tv = t[r0 >> shift];
            float a  = alpha[tv];
            float C  = __fdividef((1.0f - a) + EPSF, a + EPSF);

            int2 x = *reinterpret_cast<const int2*>(src + r0);

            float2 o;
            o.x = sample_one(r0 + 0, x.x, C, a, ka, kb, N, MASK);
            o.y = sample_one(r0 + 1, x.y, C, a, ka, kb, N, MASK);
            *reinterpret_cast<float2*>(out + j) = o;
        } else {
            // t passthrough (tiny tail; scalar)
            #pragma unroll
            for (int q = 0; q < 2; q++) {
                int jj = j + q;
                if (jj < total) out[jj] = (float)t[jj - 2 * rows];
            }
        }
    } else {
        // generic scalar fallback (any geometry)
        for (int j = gt; j < total; j += gridDim.x * blockDim.x) {
            if (j < 2 * rows) {
                const bool isS = (j < rows);
                const int  r   = isS ? j : j - rows;
                int   tv = t[(shift >= 0) ? (r >> shift) : (r / L)];
                float a  = alpha[tv];
                float C  = __fdividef((1.0f - a) + EPSF, a + EPSF);
                if (isS) out[j] = sample_one(r, structure[r], C, a, ksa, ksb, 516, 3);
                else     out[j] = sample_one(r, sequence[r],  C, a, kqa, kqb, 33, 32);
            } else {
                out[j] = (float)t[j - 2 * rows];
            }
        }
    }
}

extern "C" void kernel_launch(void* const* d_in, const int* in_sizes, int n_in,
                              void* d_out, int out_size)
{
    // Bind by size: two largest (equal) = structure/sequence candidates
    // (disambiguated on-device); of the two small ones, t's size divides
    // rows while alpha's (T+1 = 501) does not.
    int idx[4] = {0, 1, 2, 3};
    for (int i = 0; i < 3; i++)
        for (int k = i + 1; k < 4; k++)
            if (in_sizes[idx[k]] > in_sizes[idx[i]]) {
                int tmp = idx[i]; idx[i] = idx[k]; idx[k] = tmp;
            }
    const int iA = idx[0], iB = idx[1];
    int iT = idx[3], iAl = idx[2];
    const int rows = in_sizes[iA];
    if (rows % in_sizes[iT] != 0 && rows % in_sizes[iAl] == 0) {
        int tmp = iT; iT = iAl; iAl = tmp;
    }

    const int*   pA    = (const int*)  d_in[iA];
    const int*   pB    = (const int*)  d_in[iB];
    const int*   t     = (const int*)  d_in[iT];
    const float* alpha = (const float*)d_in[iAl];
    const int    Bv    = in_sizes[iT];
    const int    L     = rows / Bv;

    int shift = -1;
    if ((L & (L - 1)) == 0) { shift = 0; while ((1 << shift) < L) shift++; }
    const int fast = (shift >= 0) && (L % 2 == 0) && (rows % 2 == 0);

    // key = jax.random.key(42) -> (0, 42)
    // partitionable (foldlike) split: key_i = (o0, o1) of F((0,42), (0, i))
    unsigned ksa, ksb, kqa, kqb;
    threefry2x32(0u, 42u, 0u, 0u, ksa, ksb);   // ks (structure)
    threefry2x32(0u, 42u, 0u, 1u, kqa, kqb);   // kq (sequence)

    const int total = 2 * rows + Bv;
    int blocks;
    if (fast) {
        const int groups = (total + 1) / 2;
        blocks = (groups + 255) / 256;
    } else {
        blocks = (total + 255) / 256;
        if (blocks > 2048) blocks = 2048;
    }

    d3pm_kernel<<<blocks, 256>>>(
        pA, pB, t, alpha, (float*)d_out,
        ksa, ksb, kqa, kqb, rows, Bv, shift, L, fast);
}

// round 15
// speedup vs baseline: 1.6738x; 1.6738x over previous
#include <cuda_runtime.h>
#include <cstdint>

// D3PM q_sample — bit-exact vs JAX threefry, partitionable mode:
//   split:  key_i = (o0, o1) of threefry2x32((0,42), (0, i))     [foldlike]
//   bits32: bits[i] = o0 ^ o1 of threefry2x32(key, (0, flat_idx)),
//           flat_idx row-major over (B, L, N).
//
// Output (float32): [0,R) noised_structure, [R,2R) noised_sequence, [2R,2R+B) t.
//
// Pruning theorem (exact): argmax of gumbel+logits is ALWAYS x0 or MASK ->
// 2 RNG draws per element. Ties -> lower class index.
//
// R14 lesson: kernel is ALU-pipe bound; savings must stay off the ALU pipe and
// control flow must stay flat. This round:
//  - fast path decides via MUFU: w = -__logf(f) (2 instrs vs ~22 libdevice),
//    branchless select on diff = w2 - w1*C, C = (1-a+eps)/(a+eps).
//  - uncertainty band covers ALL fp32/MUFU error sources:
//      band = 1e-4*|thr| + 1e-6*(1+C)
//    (MUFU.LG2 abs err ~2^-21 scaled by (1+C); rel errs of C, mul, and the
//     reference's own outer-logf rounding all < 1e-5 relative).
//  - inside the band (P ~ 1e-4): __noinline__ exact fallback replicating the
//    reference bit-for-bit (libdevice logf chain + first-max tie-break).

#define TINYF  1.17549435e-38f
#define EPSF   1e-10f

__host__ __device__ __forceinline__ unsigned rotl32(unsigned x, int r) {
#ifdef __CUDA_ARCH__
    return __funnelshift_l(x, x, r);
#else
    return (x << r) | (x >> (32 - r));
#endif
}

// Standard threefry2x32, 20 rounds (matches jax/_src/prng.py lowering).
__host__ __device__ __forceinline__ void threefry2x32(
    unsigned k0, unsigned k1, unsigned m0, unsigned m1,
    unsigned& o0, unsigned& o1)
{
    const unsigned ks2 = 0x1BD11BDAu ^ k0 ^ k1;
    unsigned x0 = m0 + k0;
    unsigned x1 = m1 + k1;
#define TF_R(r) { x0 += x1; x1 = rotl32(x1, (r)) ^ x0; }
    TF_R(13) TF_R(15) TF_R(26) TF_R(6)
    x0 += k1;  x1 += ks2 + 1u;
    TF_R(17) TF_R(29) TF_R(16) TF_R(24)
    x0 += ks2; x1 += k0 + 2u;
    TF_R(13) TF_R(15) TF_R(26) TF_R(6)
    x0 += k0;  x1 += k1 + 3u;
    TF_R(17) TF_R(29) TF_R(16) TF_R(24)
    x0 += k1;  x1 += ks2 + 4u;
    TF_R(13) TF_R(15) TF_R(26) TF_R(6)
    x0 += ks2; x1 += k0 + 5u;
#undef TF_R
    o0 = x0; o1 = x1;
}

__device__ __forceinline__ unsigned jax_bits32(unsigned ka, unsigned kb, unsigned i) {
    unsigned o0, o1;
    threefry2x32(ka, kb, 0u, i, o0, o1);
    return o0 ^ o1;
}

// f stage, bit-identical to the reference's clamped uniform:
//   u = bitcast((bits>>9)|0x3f800000)-1; f = max(tiny, u+tiny)  [(1-tiny)->1.0f]
__device__ __forceinline__ float f_from_bits(unsigned bits) {
    float u = __uint_as_float(0x3f800000u | (bits >> 9)) - 1.0f;
    return fmaxf(TINYF, u + TINYF);
}

// Exact decision, replicating the reference computation bit-for-bit.
// Out of line: only executed inside the uncertainty band (P ~ 1e-4).
__device__ __noinline__ float exact_decide(
    unsigned b1, unsigned b2, float a, int x0, int MASK)
{
    float f1 = f_from_bits(b1);
    float f2 = f_from_bits(b2);
    float vx = -logf(-logf(f1)) + logf(a + EPSF);
    float vm = -logf(-logf(f2)) + logf((1.0f - a) + EPSF);
    if (vx > vm) return (float)x0;
    if (vm > vx) return (float)MASK;
    return (float)((x0 < MASK) ? x0 : MASK);   // argmax first-max tie-break
}

// One element. C = (1-a+eps)/(a+eps); bandK = 1e-6*(1+C) precomputed per pair.
__device__ __forceinline__ float sample_one(
    int r, int x0, float C, float bandK, float a,
    unsigned ka, unsigned kb, int N, int MASK)
{
    if (x0 == MASK) return (float)x0;   // combined channel always wins
    unsigned base = (unsigned)r * (unsigned)N;
    unsigned b1 = jax_bits32(ka, kb, base + (unsigned)x0);
    unsigned b2 = jax_bits32(ka, kb, base + (unsigned)MASK);

    // fast approximate w = -log(f) via MUFU
    float w1 = -__logf(f_from_bits(b1));
    float w2 = -__logf(f_from_bits(b2));

    float thr  = w1 * C;
    float diff = w2 - thr;
    float band = 1e-4f * thr + bandK;       // thr >= 0 always

    float res = (diff > 0.0f) ? (float)x0 : (float)MASK;
    if (fabsf(diff) <= band)
        res = exact_decide(b1, b2, a, x0, MASK);
    return res;
}

__global__ __launch_bounds__(256)
void d3pm_kernel(const int* __restrict__ pA, const int* __restrict__ pB,
                 const int* __restrict__ t, const float* __restrict__ alpha,
                 float* __restrict__ out,
                 unsigned ksa, unsigned ksb,
                 unsigned kqa, unsigned kqb,
                 int rows, int Bv, int shift, int L, int fast)
{
    // per-warp swap detect (no block sync): which big array is structure?
    // (sequence values always <= 32; structure exceeds 32 w.p. 1-8e-20)
    int lane = threadIdx.x & 31;
    int v = (lane < 16) ? pA[lane] : pB[lane - 16];
    unsigned big = __ballot_sync(0xffffffffu, v > 32);
    const bool swap = ((big & 0xFFFFu) == 0u);
    const int* structure = swap ? pB : pA;
    const int* sequence  = swap ? pA : pB;

    const int total = 2 * rows + Bv;
    const int gt    = blockIdx.x * blockDim.x + threadIdx.x;

    if (fast) {
        // 2 elements per thread; groups 2-aligned, never straddle segments
        // (rows % 2 == 0) nor batch boundaries (L % 2 == 0, r0 even).
        int j = gt * 2;
        if (j >= total) return;

        if (j < 2 * rows) {
            const bool isS = (j < rows);
            const int  r0  = isS ? j : j - rows;
            const int  N    = isS ? 516 : 33;
            const int  MASK = isS ? 3   : 32;
            const unsigned ka = isS ? ksa : kqa;
            const unsigned kb = isS ? ksb : kqb;
            const int* src = isS ? structure : sequence;

            // one batch per pair: one t/alpha load, one division, one bandK
            int   tv = t[r0 >> shift];
            float a  = alpha[tv];
            float C  = __fdividef((1.0f - a) + EPSF, a + EPSF);
            float bandK = 1e-6f * (1.0f + C);

            int2 x = *reinterpret_cast<const int2*>(src + r0);

            float2 o;
            o.x = sample_one(r0 + 0, x.x, C, bandK, a, ka, kb, N, MASK);
            o.y = sample_one(r0 + 1, x.y, C, bandK, a, ka, kb, N, MASK);
            *reinterpret_cast<float2*>(out + j) = o;
        } else {
            // t passthrough (tiny tail; scalar)
            #pragma unroll
            for (int q = 0; q < 2; q++) {
                int jj = j + q;
                if (jj < total) out[jj] = (float)t[jj - 2 * rows];
            }
        }
    } else {
        // generic fallback (any geometry): exact everywhere
        for (int j = gt; j < total; j += gridDim.x * blockDim.x) {
            if (j < 2 * rows) {
                const bool isS = (j < rows);
                const int  r   = isS ? j : j - rows;
                int   tv = t[(shift >= 0) ? (r >> shift) : (r / L)];
                float a  = alpha[tv];
                int   x0   = isS ? structure[r] : sequence[r];
                int   N    = isS ? 516 : 33;
                int   MASK = isS ? 3   : 32;
                unsigned ka = isS ? ksa : kqa;
                unsigned kb = isS ? ksb : kqb;
                if (x0 == MASK) { out[j] = (float)x0; continue; }
                unsigned base = (unsigned)r * (unsigned)N;
                unsigned b1 = jax_bits32(ka, kb, base + (unsigned)x0);
                unsigned b2 = jax_bits32(ka, kb, base + (unsigned)MASK);
                out[j] = exact_decide(b1, b2, a, x0, MASK);
            } else {
                out[j] = (float)t[j - 2 * rows];
            }
        }
    }
}

extern "C" void kernel_launch(void* const* d_in, const int* in_sizes, int n_in,
                              void* d_out, int out_size)
{
    // Bind by size: two largest (equal) = structure/sequence candidates
    // (disambiguated on-device); of the two small ones, t's size divides
    // rows while alpha's (T+1 = 501) does not.
    int idx[4] = {0, 1, 2, 3};
    for (int i = 0; i < 3; i++)
        for (int k = i + 1; k < 4; k++)
            if (in_sizes[idx[k]] > in_sizes[idx[i]]) {
                int tmp = idx[i]; idx[i] = idx[k]; idx[k] = tmp;
            }
    const int iA = idx[0], iB = idx[1];
    int iT = idx[3], iAl = idx[2];
    const int rows = in_sizes[iA];
    if (rows % in_sizes[iT] != 0 && rows % in_sizes[iAl] == 0) {
        int tmp = iT; iT = iAl; iAl = tmp;
    }

    const int*   pA    = (const int*)  d_in[iA];
    const int*   pB    = (const int*)  d_in[iB];
    const int*   t     = (const int*)  d_in[iT];
    const float* alpha = (const float*)d_in[iAl];
    const int    Bv    = in_sizes[iT];
    const int    L     = rows / Bv;

    int shift = -1;
    if ((L & (L - 1)) == 0) { shift = 0; while ((1 << shift) < L) shift++; }
    const int fast = (shift >= 0) && (L % 2 == 0) && (rows % 2 == 0);

    // key = jax.random.key(42) -> (0, 42)
    // partitionable (foldlike) split: key_i = (o0, o1) of F((0,42), (0, i))
    unsigned ksa, ksb, kqa, kqb;
    threefry2x32(0u, 42u, 0u, 0u, ksa, ksb);   // ks (structure)
    threefry2x32(0u, 42u, 0u, 1u, kqa, kqb);   // kq (sequence)

    const int total = 2 * rows + Bv;
    int blocks;
    if (fast) {
        const int groups = (total + 1) / 2;
        blocks = (groups + 255) / 256;
    } else {
        blocks = (total + 255) / 256;
        if (blocks > 2048) blocks = 2048;
    }

    d3pm_kernel<<<blocks, 256>>>(
        pA, pB, t, alpha, (float*)d_out,
        ksa, ksb, kqa, kqb, rows, Bv, shift, L, fast);
}